// round 14
// baseline (speedup 1.0000x reference)
#include <cuda_runtime.h>
#include <cuda_bf16.h>
#include <math.h>
#include <stdint.h>

// Problem constants
#define Dm   1024
#define Sm   4096
#define Bb   2
#define DIm  4096
#define NT   (Bb*Sm)       // 8192 token rows
#define KTOP 32
#define Am   64

// ---------------------------------------------------------------------------
// Scratch. Packed operands: bf16 PLANES [hi (rows*K)][lo (rows*K)].
// ---------------------------------------------------------------------------
__device__ float g_xn [NT*Dm];
__device__ float g_vrv[(size_t)3*NT*Dm];           // v | r | vsa (z-batched out)
__device__ float g_x1 [NT*Dm];
__device__ float g_qk [(size_t)NT*128];            // q||k fused projection
__device__ float g_big[(size_t)NT*Sm];             // scores
__device__ float g_b3 [3*Dm];                      // per-z bias for batched gemm
__device__ float g_qkb[128];                       // fused q/k bias
__device__ __align__(16) __nv_bfloat16 g_pAct[(size_t)6*NT*Dm];   // 3 slots x [hi|lo]
__device__ __align__(16) __nv_bfloat16 g_pBIG[(size_t)2*NT*DIm];
__device__ __align__(16) __nv_bfloat16 g_pQ  [(size_t)2*NT*Am];
__device__ __align__(16) __nv_bfloat16 g_pK  [(size_t)2*NT*Am];
// weight arena: 6 DxD slots (2 planes each) then 2 DIxD slots
__device__ __align__(16) __nv_bfloat16 g_wAll[(size_t)12*Dm*Dm + (size_t)4*DIm*Dm];
__device__ __align__(16) __nv_bfloat16 g_wqk [(size_t)2*128*Dm];  // fused qk weights

// ---------------------------------------------------------------------------
// PTX helpers (legal at compute_103)
// ---------------------------------------------------------------------------
__device__ __forceinline__ uint32_t smem_u32(const void* p) {
    uint32_t a;
    asm("{ .reg .u64 t; cvta.to.shared.u64 t, %1; cvt.u32.u64 %0, t; }" : "=r"(a) : "l"(p));
    return a;
}
__device__ __forceinline__ uint32_t sw128(uint32_t o) { return o ^ ((o >> 3) & 0x70); }

__device__ __forceinline__ void cp16(uint32_t s, const void* g) {
    asm volatile("cp.async.cg.shared.global [%0], [%1], 16;" :: "r"(s), "l"(g));
}
__device__ __forceinline__ void cp_commit() { asm volatile("cp.async.commit_group;" ::: "memory"); }
__device__ __forceinline__ void cp_wait0()  { asm volatile("cp.async.wait_group 0;" ::: "memory"); }
__device__ __forceinline__ void cp_wait1()  { asm volatile("cp.async.wait_group 1;" ::: "memory"); }

__device__ __forceinline__ void ldsm4(uint32_t* r, uint32_t a) {
    asm volatile("ldmatrix.sync.aligned.m8n8.x4.shared.b16 {%0,%1,%2,%3}, [%4];"
                 : "=r"(r[0]), "=r"(r[1]), "=r"(r[2]), "=r"(r[3]) : "r"(a));
}
__device__ __forceinline__ void mma16816(float* c, const uint32_t* a, uint32_t b0, uint32_t b1) {
    asm volatile(
        "mma.sync.aligned.m16n8k16.row.col.f32.bf16.bf16.f32 "
        "{%0,%1,%2,%3}, {%4,%5,%6,%7}, {%8,%9}, {%0,%1,%2,%3};"
        : "+f"(c[0]), "+f"(c[1]), "+f"(c[2]), "+f"(c[3])
        : "r"(a[0]), "r"(a[1]), "r"(a[2]), "r"(a[3]), "r"(b0), "r"(b1));
}

__device__ __forceinline__ void split2(float v0, float v1,
                                       __nv_bfloat162& hp, __nv_bfloat162& lp) {
    __nv_bfloat16 h0 = __float2bfloat16_rn(v0);
    __nv_bfloat16 h1 = __float2bfloat16_rn(v1);
    __nv_bfloat16 l0 = __float2bfloat16_rn(v0 - __bfloat162float(h0));
    __nv_bfloat16 l1 = __float2bfloat16_rn(v1 - __bfloat162float(h1));
    hp.x = h0; hp.y = h1; lp.x = l0; lp.y = l1;
}

// ---------------------------------------------------------------------------
// mma.sync NT GEMM on hi/lo planes: C = alpha*(Ahi·Bhi + Alo·Bhi + Ahi·Blo)
// CTA tile 128xBN, warp tile 64x(BN/4), BK=64, 2-stage cp.async.
// mode: 0 = fp32 (+resid), 1 = pack, 2 = relu^2 + pack,
//       3 = gate-pack:  pack( sigmoid(gate)*(acc+bias+resid) )
//       4 = gate-final: fp32( resid + sigmoid(gate)*(acc+bias) )
// ---------------------------------------------------------------------------
template <int BN>
__global__ void __launch_bounds__(256, 1) mma_gemm(
    const __nv_bfloat16* __restrict__ Ap, long aLo,
    const __nv_bfloat16* __restrict__ Bp, long bLo,
    float* __restrict__ C, int N, int K,
    long sA, long sB, long sC,
    const float* __restrict__ bias, long sBias,
    const float* __restrict__ resid, const float* __restrict__ gate,
    float alpha, int mode, long pOfs)
{
    constexpr int NTN = BN / 32;                   // acc n-tiles
    constexpr int NTP = BN / 64;                   // b ldsm groups
    constexpr uint32_t stALo = 16384u;
    constexpr uint32_t stBhi = 32768u;
    constexpr uint32_t stBlo = 32768u + BN * 128u;
    constexpr uint32_t stSz  = 32768u + 2u * BN * 128u;

    extern __shared__ char smem[];
    const __nv_bfloat16* Ahi = Ap + (long)blockIdx.z * sA;
    const __nv_bfloat16* Alo = Ap + aLo + (long)blockIdx.z * sA;
    const __nv_bfloat16* Bhi = Bp + (long)blockIdx.z * sB;
    const __nv_bfloat16* Blo = Bp + bLo + (long)blockIdx.z * sB;
    C += (long)blockIdx.z * sC;
    if (resid) resid += (long)blockIdx.z * sC;
    if (bias)  bias  += (long)blockIdx.z * sBias;

    const int tid  = threadIdx.x;
    const int lane = tid & 31;
    const int wid  = tid >> 5;
    const int wm   = wid >> 2;                    // 0..1
    const int wn   = wid & 3;                     // 0..3
    const int row0 = blockIdx.y * 128;
    const int col0 = blockIdx.x * BN;
    const uint32_t su = smem_u32(smem);

    float acc[4][NTN][4];
    #pragma unroll
    for (int mt = 0; mt < 4; mt++)
        #pragma unroll
        for (int nt = 0; nt < NTN; nt++)
            #pragma unroll
            for (int i = 0; i < 4; i++) acc[mt][nt][i] = 0.f;

    const int nch = K >> 6;

    auto load_stage = [&](uint32_t sbase, int k0) {
        #pragma unroll
        for (int i = 0; i < 4; i++) {
            int j = tid + 256 * i; int r = j >> 3, cb = (j & 7) << 4;
            cp16(sbase + sw128((uint32_t)(r * 128 + cb)),
                 Ahi + (long)(row0 + r) * K + k0 + (cb >> 1));
        }
        #pragma unroll
        for (int i = 0; i < 4; i++) {
            int j = tid + 256 * i; int r = j >> 3, cb = (j & 7) << 4;
            cp16(sbase + stALo + sw128((uint32_t)(r * 128 + cb)),
                 Alo + (long)(row0 + r) * K + k0 + (cb >> 1));
        }
        #pragma unroll
        for (int i = 0; i < BN / 32; i++) {
            int j = tid + 256 * i; int r = j >> 3, cb = (j & 7) << 4;
            cp16(sbase + stBhi + sw128((uint32_t)(r * 128 + cb)),
                 Bhi + (long)(col0 + r) * K + k0 + (cb >> 1));
        }
        #pragma unroll
        for (int i = 0; i < BN / 32; i++) {
            int j = tid + 256 * i; int r = j >> 3, cb = (j & 7) << 4;
            cp16(sbase + stBlo + sw128((uint32_t)(r * 128 + cb)),
                 Blo + (long)(col0 + r) * K + k0 + (cb >> 1));
        }
    };

    load_stage(su, 0);
    cp_commit();

    for (int t = 0; t < nch; t++) {
        if (t + 1 < nch) {
            load_stage(su + (((t + 1) & 1) ? stSz : 0u), (t + 1) << 6);
            cp_commit();
            cp_wait1();
        } else {
            cp_wait0();
        }
        __syncthreads();

        const uint32_t sb  = su + ((t & 1) ? stSz : 0u);
        const uint32_t sAh = sb;
        const uint32_t sAl = sb + stALo;
        const uint32_t sBh = sb + stBhi;
        const uint32_t sBl = sb + stBlo;

        #pragma unroll
        for (int ks = 0; ks < 4; ks++) {
            uint32_t ahi[4][4], alo[4][4];
            #pragma unroll
            for (int mt = 0; mt < 4; mt++) {
                uint32_t off = (uint32_t)((wm * 64 + mt * 16 + (lane & 15)) * 128
                                          + ks * 32 + ((lane >> 4) << 4));
                ldsm4(ahi[mt], sAh + sw128(off));
                ldsm4(alo[mt], sAl + sw128(off));
            }
            #pragma unroll
            for (int ntp = 0; ntp < NTP; ntp++) {
                int g = lane >> 3;
                uint32_t off = (uint32_t)((wn * (BN / 4) + ntp * 16 + (lane & 7) + (g >> 1) * 8) * 128
                                          + ks * 32 + (g & 1) * 16);
                uint32_t bh[4], bl[4];
                ldsm4(bh, sBh + sw128(off));
                ldsm4(bl, sBl + sw128(off));
                #pragma unroll
                for (int s = 0; s < 2; s++)
                    #pragma unroll
                    for (int mt = 0; mt < 4; mt++)
                        mma16816(acc[mt][ntp * 2 + s], ahi[mt], bh[2 * s], bh[2 * s + 1]);
                #pragma unroll
                for (int s = 0; s < 2; s++)
                    #pragma unroll
                    for (int mt = 0; mt < 4; mt++)
                        mma16816(acc[mt][ntp * 2 + s], alo[mt], bh[2 * s], bh[2 * s + 1]);
                #pragma unroll
                for (int s = 0; s < 2; s++)
                    #pragma unroll
                    for (int mt = 0; mt < 4; mt++)
                        mma16816(acc[mt][ntp * 2 + s], ahi[mt], bl[2 * s], bl[2 * s + 1]);
            }
        }
        __syncthreads();
    }

    // epilogue
    #pragma unroll
    for (int mt = 0; mt < 4; mt++) {
        int gr0 = row0 + wm * 64 + mt * 16 + (lane >> 2);
        #pragma unroll
        for (int nt = 0; nt < NTN; nt++) {
            int gc = col0 + wn * (BN / 4) + nt * 8 + ((lane & 3) << 1);
            float b0 = 0.f, b1 = 0.f;
            if (bias) { b0 = bias[gc]; b1 = bias[gc + 1]; }
            #pragma unroll
            for (int h = 0; h < 2; h++) {
                int gr = gr0 + h * 8;
                long eidx = (long)gr * N + gc;
                float v0 = acc[mt][nt][h * 2 + 0] * alpha + b0;
                float v1 = acc[mt][nt][h * 2 + 1] * alpha + b1;
                if (mode == 2) { v0 = fmaxf(v0, 0.f); v0 *= v0;
                                 v1 = fmaxf(v1, 0.f); v1 *= v1; }
                if (mode == 3) {
                    float2 gg = *reinterpret_cast<const float2*>(gate + eidx);
                    float2 rr = *reinterpret_cast<const float2*>(resid + eidx);
                    v0 = (1.f / (1.f + expf(-gg.x))) * (v0 + rr.x);
                    v1 = (1.f / (1.f + expf(-gg.y))) * (v1 + rr.y);
                } else if (mode == 4) {
                    float2 gg = *reinterpret_cast<const float2*>(gate + eidx);
                    float2 rr = *reinterpret_cast<const float2*>(resid + eidx);
                    v0 = rr.x + (1.f / (1.f + expf(-gg.x))) * v0;
                    v1 = rr.y + (1.f / (1.f + expf(-gg.y))) * v1;
                } else if (resid && mode == 0) {
                    float2 rr = *reinterpret_cast<const float2*>(resid + eidx);
                    v0 += rr.x; v1 += rr.y;
                }
                if (mode == 1 || mode == 2 || mode == 3) {
                    __nv_bfloat16* P = reinterpret_cast<__nv_bfloat16*>(C);
                    __nv_bfloat162 hp, lp;
                    split2(v0, v1, hp, lp);
                    *reinterpret_cast<__nv_bfloat162*>(P + eidx)        = hp;
                    *reinterpret_cast<__nv_bfloat162*>(P + eidx + pOfs) = lp;
                } else {
                    *reinterpret_cast<float2*>(C + eidx) = make_float2(v0, v1);
                }
            }
        }
    }
}

// ---------------------------------------------------------------------------
// one-shot weight pack: all segments in a single launch
// ---------------------------------------------------------------------------
#define NSEG 10
struct PackDesc {
    const float*   src[NSEG];
    __nv_bfloat16* dst[NSEG];
    long           total2[NSEG];
    long           planeOfs[NSEG];
    long           blkStart[NSEG];
};

__global__ void __launch_bounds__(256) multi_pack(PackDesc pd)
{
    int seg = 0;
    #pragma unroll
    for (int s2 = NSEG - 1; s2 > 0; s2--)
        if (blockIdx.x >= pd.blkStart[s2]) { seg = s2; break; }
    long i = ((long)blockIdx.x - pd.blkStart[seg]) * 256 + threadIdx.x;
    if (i >= pd.total2[seg]) return;
    long e = i << 1;
    float2 x = *reinterpret_cast<const float2*>(pd.src[seg] + e);
    __nv_bfloat162 hp, lp;
    split2(x.x, x.y, hp, lp);
    __nv_bfloat16* d = pd.dst[seg];
    *reinterpret_cast<__nv_bfloat162*>(d + e)                   = hp;
    *reinterpret_cast<__nv_bfloat162*>(d + pd.planeOfs[seg] + e) = lp;
}

__global__ void __launch_bounds__(256) fill_b3(
    const float* __restrict__ vb, float* __restrict__ b3)
{
    int i = blockIdx.x * 256 + threadIdx.x;
    if (i < 3 * Dm) b3[i] = (i < 2 * Dm) ? 0.f : vb[i - 2 * Dm];
}

__global__ void __launch_bounds__(128) fill_qkb(
    const float* __restrict__ qb, const float* __restrict__ kb, float* __restrict__ o)
{
    int i = threadIdx.x;
    o[i] = (i < 64) ? qb[i] : kb[i - 64];
}

// split fused qk buffer -> pQ (A planes) and pK (B planes)
__global__ void __launch_bounds__(256) pack_qk(
    const float* __restrict__ qk, __nv_bfloat16* __restrict__ pQ,
    __nv_bfloat16* __restrict__ pK, long planeOfs)
{
    long i2 = (long)blockIdx.x * 256 + threadIdx.x;
    long idx = i2 << 1;
    if (idx >= (long)NT * Am) return;
    long row = idx >> 6;
    int  c = (int)(idx & 63);
    float2 qv = *reinterpret_cast<const float2*>(qk + row * 128 + c);
    float2 kv = *reinterpret_cast<const float2*>(qk + row * 128 + 64 + c);
    __nv_bfloat162 hp, lp;
    long e = row * Am + c;
    split2(qv.x, qv.y, hp, lp);
    *reinterpret_cast<__nv_bfloat162*>(pQ + e)            = hp;
    *reinterpret_cast<__nv_bfloat162*>(pQ + planeOfs + e) = lp;
    split2(kv.x, kv.y, hp, lp);
    *reinterpret_cast<__nv_bfloat162*>(pK + e)            = hp;
    *reinterpret_cast<__nv_bfloat162*>(pK + planeOfs + e) = lp;
}

// ---------------------------------------------------------------------------
// rmsnorm: fp32 out + optional hi/lo plane out
// ---------------------------------------------------------------------------
__global__ void __launch_bounds__(256) rmsnorm_k(
    const float* __restrict__ x, const float* __restrict__ w,
    float* __restrict__ out, __nv_bfloat16* __restrict__ pk, long planeOfs)
{
    int row = blockIdx.x;
    const float* xr = x + (long)row * Dm;
    int tid = threadIdx.x;
    float ss = 0.f;
    #pragma unroll
    for (int d = tid; d < Dm; d += 256) { float v = xr[d]; ss += v * v; }
    __shared__ float red[256];
    red[tid] = ss; __syncthreads();
    for (int o = 128; o; o >>= 1) {
        if (tid < o) red[tid] += red[tid + o];
        __syncthreads();
    }
    float scale = 1.f / (sqrtf(red[0] * (1.f / Dm)) + 1e-8f);
    #pragma unroll
    for (int d = tid; d < Dm; d += 256) {
        float v = w[d] * xr[d] * scale;
        long e = (long)row * Dm + d;
        out[e] = v;
        if (pk) {
            __nv_bfloat16 h = __float2bfloat16_rn(v);
            __nv_bfloat16 l = __float2bfloat16_rn(v - __bfloat162float(h));
            pk[e] = h; pk[e + planeOfs] = l;
        }
    }
}

// ---------------------------------------------------------------------------
// token-shift mixes -> two hi/lo-plane packed A operands
// ---------------------------------------------------------------------------
__global__ void __launch_bounds__(256) mix2pack_k(
    const float* __restrict__ xn, const float* __restrict__ m1,
    const float* __restrict__ m2,
    __nv_bfloat16* __restrict__ p1, __nv_bfloat16* __restrict__ p2, long planeOfs)
{
    long pi2 = (long)blockIdx.x * 256 + threadIdx.x;
    long i = pi2 << 1;
    int d = (int)(i & (Dm - 1));
    int s = (int)((i >> 10) & (Sm - 1));
    long prev = s ? (i - Dm) : i;
    float2 cur = *reinterpret_cast<const float2*>(xn + i);
    float2 prv = *reinterpret_cast<const float2*>(xn + prev);
    float a0 = m1[d], a1 = m1[d + 1];
    float b0 = m2[d], b1 = m2[d + 1];
    float o10 = cur.x * a0 + prv.x * (1.f - a0);
    float o11 = cur.y * a1 + prv.y * (1.f - a1);
    float o20 = cur.x * b0 + prv.x * (1.f - b0);
    float o21 = cur.y * b1 + prv.y * (1.f - b1);
    __nv_bfloat162 hp, lp;
    split2(o10, o11, hp, lp);
    *reinterpret_cast<__nv_bfloat162*>(p1 + i)            = hp;
    *reinterpret_cast<__nv_bfloat162*>(p1 + planeOfs + i) = lp;
    split2(o20, o21, hp, lp);
    *reinterpret_cast<__nv_bfloat162*>(p2 + i)            = hp;
    *reinterpret_cast<__nv_bfloat162*>(p2 + planeOfs + i) = lp;
}

// ---------------------------------------------------------------------------
// top-32 (owner-rescan) + softmax + V-gather -> hi/lo planes
// ---------------------------------------------------------------------------
__global__ void __launch_bounds__(128) topk_attn_k(
    const float* __restrict__ Sc, const float* __restrict__ Vsa,
    __nv_bfloat16* __restrict__ OutP, long planeOfs)
{
    int q = blockIdx.x;
    int b = q >> 12;
    const float* srow = Sc + (long)q * Sm;

    __shared__ float topv[KTOP];
    __shared__ int   topi[KTOP];
    __shared__ float wmv[4];
    __shared__ int   wiv[4];
    __shared__ int   sel;
    __shared__ float p[KTOP];

    const int tid  = threadIdx.x;
    const int lane = tid & 31;
    const int wrp  = tid >> 5;

    float sv[32];
    #pragma unroll
    for (int i = 0; i < 32; i++) sv[i] = srow[tid + (i << 7)];

    float best = -INFINITY; int bloc = 0;
    #pragma unroll
    for (int i = 0; i < 32; i++)
        if (sv[i] > best) { best = sv[i]; bloc = i; }

    for (int it = 0; it < KTOP; it++) {
        float cb = best;
        int   ci = tid + (bloc << 7);
        #pragma unroll
        for (int o = 16; o; o >>= 1) {
            float ov = __shfl_down_sync(0xffffffffu, cb, o);
            int   oi = __shfl_down_sync(0xffffffffu, ci, o);
            if (ov > cb || (ov == cb && oi < ci)) { cb = ov; ci = oi; }
        }
        if (lane == 0) { wmv[wrp] = cb; wiv[wrp] = ci; }
        __syncthreads();
        if (tid == 0) {
            float bb = wmv[0]; int bj = wiv[0];
            #pragma unroll
            for (int w2 = 1; w2 < 4; w2++)
                if (wmv[w2] > bb || (wmv[w2] == bb && wiv[w2] < bj)) { bb = wmv[w2]; bj = wiv[w2]; }
            topv[it] = bb; topi[it] = bj; sel = bj;
        }
        __syncthreads();
        int bj = sel;
        if ((bj & 127) == tid) {
            sv[bj >> 7] = -INFINITY;
            best = -INFINITY; bloc = 0;
            #pragma unroll
            for (int i = 0; i < 32; i++)
                if (sv[i] > best) { best = sv[i]; bloc = i; }
        }
        __syncthreads();
    }

    if (tid == 0) {
        float mx = topv[0], Z = 0.f;
        #pragma unroll
        for (int i2 = 0; i2 < KTOP; i2++) { float e = expf(topv[i2] - mx); p[i2] = e; Z += e; }
        float iz = 1.f / Z;
        #pragma unroll
        for (int i2 = 0; i2 < KTOP; i2++) p[i2] *= iz;
    }
    __syncthreads();

    const float* Vb = Vsa + (long)b * Sm * Dm;
    for (int d = tid; d < Dm; d += 128) {
        float acc = 0.f;
        #pragma unroll
        for (int i2 = 0; i2 < KTOP; i2++)
            acc += p[i2] * Vb[(long)topi[i2] * Dm + d];
        __nv_bfloat16 h = __float2bfloat16_rn(acc);
        __nv_bfloat16 l = __float2bfloat16_rn(acc - __bfloat162float(h));
        long e = (long)q * Dm + d;
        OutP[e] = h; OutP[e + planeOfs] = l;
    }
}

// ---------------------------------------------------------------------------
// launcher
// ---------------------------------------------------------------------------
extern "C" void kernel_launch(void* const* d_in, const int* in_sizes, int n_in,
                              void* d_out, int out_size)
{
    const float* x           = (const float*)d_in[0];
    const float* norm1_w     = (const float*)d_in[1];
    const float* tm_mix_v    = (const float*)d_in[3];
    const float* tm_mix_r    = (const float*)d_in[4];
    // d_in[2]=tm_mix_k, d_in[5]=tm_key_w: dead in reference
    const float* tm_value_w  = (const float*)d_in[6];
    const float* tm_recept_w = (const float*)d_in[7];
    const float* tm_out_w    = (const float*)d_in[8];
    const float* sa_q_w      = (const float*)d_in[9];
    const float* sa_q_b      = (const float*)d_in[10];
    const float* sa_k_w      = (const float*)d_in[11];
    const float* sa_k_b      = (const float*)d_in[12];
    const float* sa_v_w      = (const float*)d_in[13];
    const float* sa_v_b      = (const float*)d_in[14];
    const float* sa_o_w      = (const float*)d_in[15];
    const float* sa_o_b      = (const float*)d_in[16];
    const float* norm2_w     = (const float*)d_in[17];
    const float* cm_mix_k    = (const float*)d_in[18];
    const float* cm_mix_r    = (const float*)d_in[19];
    const float* cm_key_w    = (const float*)d_in[20];
    const float* cm_recept_w = (const float*)d_in[21];
    const float* cm_value_w  = (const float*)d_in[22];
    float* out = (float*)d_out;

    float *xn, *vrv, *x1, *qk, *big, *b3, *qkb;
    __nv_bfloat16 *pAct, *pBIG, *pQ, *pK, *wAll, *wqk;
    cudaGetSymbolAddress((void**)&xn,   g_xn);
    cudaGetSymbolAddress((void**)&vrv,  g_vrv);
    cudaGetSymbolAddress((void**)&x1,   g_x1);
    cudaGetSymbolAddress((void**)&qk,   g_qk);
    cudaGetSymbolAddress((void**)&big,  g_big);
    cudaGetSymbolAddress((void**)&b3,   g_b3);
    cudaGetSymbolAddress((void**)&qkb,  g_qkb);
    cudaGetSymbolAddress((void**)&pAct, g_pAct);
    cudaGetSymbolAddress((void**)&pBIG, g_pBIG);
    cudaGetSymbolAddress((void**)&pQ,   g_pQ);
    cudaGetSymbolAddress((void**)&pK,   g_pK);
    cudaGetSymbolAddress((void**)&wAll, g_wAll);
    cudaGetSymbolAddress((void**)&wqk,  g_wqk);

    cudaFuncSetAttribute(mma_gemm<256>, cudaFuncAttributeMaxDynamicSharedMemorySize, 196608);
    cudaFuncSetAttribute(mma_gemm<128>, cudaFuncAttributeMaxDynamicSharedMemorySize, 131072);

    const long ofsD  = (long)NT * Dm;            // activation plane size
    const long ofsDI = (long)NT * DIm;
    const long ofsA  = (long)NT * Am;
    const long slot  = 2 * ofsD;                 // z-slot stride in pAct
    const long W_DD  = 2L * Dm * Dm;             // DxD weight slot (2 planes)
    const long W_DI  = 2L * DIm * Dm;
    __nv_bfloat16* pS0 = pAct;                   // mix1 / att / cm mix1
    __nv_bfloat16* pS1 = pAct + slot;            // mix2 / rkv / cm mix2
    __nv_bfloat16* pS2 = pAct + 2 * slot;        // xn packed
    // weight slots
    __nv_bfloat16* w_tmv = wAll;                 // slots 0..2 consecutive (batched)
    __nv_bfloat16* w_sao = wAll + 3 * W_DD;
    __nv_bfloat16* w_tmo = wAll + 4 * W_DD;
    __nv_bfloat16* w_cmr = wAll + 5 * W_DD;
    __nv_bfloat16* w_cmk = wAll + 6 * W_DD;
    __nv_bfloat16* w_cmv = wAll + 6 * W_DD + W_DI;

    const dim3 gD (Dm / 256,  NT / 128);          // (4, 64)
    const dim3 gD3(Dm / 256,  NT / 128, 3);       // batched v/r/vsa
    const dim3 gDI(DIm / 256, NT / 128);          // (16, 64)
    const dim3 gS (Sm / 256,  Sm / 128, Bb);      // (16, 32, 2)
    const dim3 gQK(1, NT / 128);                  // fused q/k, BN=128
    const int  pairBlocks = NT * Dm / 512;

    // ---- single-launch weight pack (10 segments) ----
    {
        PackDesc pd;
        const float* srcs[NSEG] = { tm_value_w, tm_recept_w, sa_v_w, sa_o_w, tm_out_w,
                                    cm_recept_w, cm_key_w, cm_value_w, sa_q_w, sa_k_w };
        __nv_bfloat16* dsts[NSEG] = { w_tmv, wAll + W_DD, wAll + 2 * W_DD, w_sao, w_tmo,
                                      w_cmr, w_cmk, w_cmv, wqk, wqk + 64 * Dm };
        long tots[NSEG] = { Dm*(long)Dm/2, Dm*(long)Dm/2, Dm*(long)Dm/2, Dm*(long)Dm/2,
                            Dm*(long)Dm/2, Dm*(long)Dm/2, DIm*(long)Dm/2, DIm*(long)Dm/2,
                            64L*Dm/2, 64L*Dm/2 };
        long pofs[NSEG] = { (long)Dm*Dm, (long)Dm*Dm, (long)Dm*Dm, (long)Dm*Dm,
                            (long)Dm*Dm, (long)Dm*Dm, (long)DIm*Dm, (long)DIm*Dm,
                            128L*Dm, 128L*Dm };
        long bs = 0;
        for (int s2 = 0; s2 < NSEG; s2++) {
            pd.src[s2] = srcs[s2]; pd.dst[s2] = dsts[s2];
            pd.total2[s2] = tots[s2]; pd.planeOfs[s2] = pofs[s2];
            pd.blkStart[s2] = bs;
            bs += (tots[s2] + 255) / 256;
        }
        multi_pack<<<(unsigned)bs, 256>>>(pd);
    }
    fill_b3<<<(3 * Dm + 255) / 256, 256>>>(sa_v_b, b3);
    fill_qkb<<<1, 128>>>(sa_q_b, sa_k_b, qkb);

    // ---- time mix ----
    rmsnorm_k<<<NT, 256>>>(x, norm1_w, xn, pS2, ofsD);
    mix2pack_k<<<pairBlocks, 256>>>(xn, tm_mix_v, tm_mix_r, pS0, pS1, ofsD);

    // batched v / r / vsa
    mma_gemm<256><<<gD3, 256, 196608>>>(pAct, ofsD, wAll, (long)Dm * Dm, vrv, Dm, Dm,
                                        slot, W_DD, ofsD, b3, Dm, nullptr, nullptr,
                                        1.f, 0, 0);
    float* v   = vrv;
    float* r   = vrv + ofsD;
    float* vsa = vrv + 2 * ofsD;

    // fused q/k projection (BN=128)
    mma_gemm<128><<<gQK, 256, 131072>>>(pS2, ofsD, wqk, 128L * Dm, qk, 128, Dm,
                                        0, 0, 0, qkb, 0, nullptr, nullptr,
                                        1.f, 0, 0);
    pack_qk<<<(int)((ofsA / 2 + 255) / 256), 256>>>(qk, pQ, pK, ofsA);

    // scores
    mma_gemm<256><<<gS, 256, 196608>>>(pQ, ofsA, pK, ofsA, big, Sm, Am,
                                       (long)Sm * Am, (long)Sm * Am, (long)Sm * Sm,
                                       nullptr, 0, nullptr, nullptr,
                                       0.125f, 0, 0);

    topk_attn_k<<<NT, 128>>>(big, vsa, pS0, ofsD);

    // O-projection with fused rkv-gate + pack -> pS1 planes
    mma_gemm<256><<<gD, 256, 196608>>>(pS0, ofsD, w_sao, (long)Dm * Dm, (float*)pS1, Dm, Dm,
                                       0, 0, 0, sa_o_b, 0, v, r,
                                       1.f, 3, ofsD);

    // x1 = rkv @ tm_out + x
    mma_gemm<256><<<gD, 256, 196608>>>(pS1, ofsD, w_tmo, (long)Dm * Dm, x1, Dm, Dm,
                                       0, 0, 0, nullptr, 0, x, nullptr,
                                       1.f, 0, 0);

    // ---- channel mix ----
    rmsnorm_k<<<NT, 256>>>(x1, norm2_w, xn, nullptr, 0);
    mix2pack_k<<<pairBlocks, 256>>>(xn, cm_mix_k, cm_mix_r, pS0, pS1, ofsD);

    // k2 = relu^2(mix1 @ cm_key) -> packed
    mma_gemm<256><<<gDI, 256, 196608>>>(pS0, ofsD, w_cmk, (long)DIm * Dm, (float*)pBIG, DIm, Dm,
                                        0, 0, 0, nullptr, 0, nullptr, nullptr,
                                        1.f, 2, ofsDI);

    // r2 = mix2 @ cm_recept
    mma_gemm<256><<<gD, 256, 196608>>>(pS1, ofsD, w_cmr, (long)Dm * Dm, r, Dm, Dm,
                                       0, 0, 0, nullptr, 0, nullptr, nullptr,
                                       1.f, 0, 0);

    // out = x1 + sigmoid(r2) * (k2 @ cm_value)   [fused final]
    mma_gemm<256><<<gD, 256, 196608>>>(pBIG, ofsDI, w_cmv, (long)DIm * Dm, out, Dm, DIm,
                                       0, 0, 0, nullptr, 0, x1, r,
                                       1.f, 4, 0);
}

// round 16
// speedup vs baseline: 1.0700x; 1.0700x over previous
#include <cuda_runtime.h>
#include <cuda_bf16.h>
#include <math.h>
#include <stdint.h>

// Problem constants
#define Dm   1024
#define Sm   4096
#define Bb   2
#define DIm  4096
#define NT   (Bb*Sm)       // 8192 token rows
#define KTOP 32
#define Am   64

// ---------------------------------------------------------------------------
// Scratch. Packed operands: bf16 PLANES [hi (rows*K)][lo (rows*K)].
// ---------------------------------------------------------------------------
__device__ float g_xn [NT*Dm];
__device__ float g_vrv[(size_t)3*NT*Dm];           // v | r | vsa (z-batched out)
__device__ float g_ao [NT*Dm];
__device__ float g_x1 [NT*Dm];
__device__ float g_qk [(size_t)NT*128];            // q||k fused projection
__device__ float g_big[(size_t)NT*Sm];             // scores
__device__ float g_b3 [3*Dm];                      // per-z bias for batched gemm
__device__ float g_qkb[128];                       // fused q/k bias
__device__ __align__(16) __nv_bfloat16 g_pAct[(size_t)6*NT*Dm];   // 3 slots x [hi|lo]
__device__ __align__(16) __nv_bfloat16 g_pBIG[(size_t)2*NT*DIm];
__device__ __align__(16) __nv_bfloat16 g_pQ  [(size_t)2*NT*Am];
__device__ __align__(16) __nv_bfloat16 g_pK  [(size_t)2*NT*Am];
// weight arena: 6 DxD slots (2 planes each) then 2 DIxD slots
__device__ __align__(16) __nv_bfloat16 g_wAll[(size_t)12*Dm*Dm + (size_t)4*DIm*Dm];
__device__ __align__(16) __nv_bfloat16 g_wqk [(size_t)2*128*Dm];  // fused qk weights

// ---------------------------------------------------------------------------
// PTX helpers (legal at compute_103)
// ---------------------------------------------------------------------------
__device__ __forceinline__ uint32_t smem_u32(const void* p) {
    uint32_t a;
    asm("{ .reg .u64 t; cvta.to.shared.u64 t, %1; cvt.u32.u64 %0, t; }" : "=r"(a) : "l"(p));
    return a;
}
__device__ __forceinline__ uint32_t sw128(uint32_t o) { return o ^ ((o >> 3) & 0x70); }

__device__ __forceinline__ void cp16(uint32_t s, const void* g) {
    asm volatile("cp.async.cg.shared.global [%0], [%1], 16;" :: "r"(s), "l"(g));
}
__device__ __forceinline__ void cp_commit() { asm volatile("cp.async.commit_group;" ::: "memory"); }
__device__ __forceinline__ void cp_wait0()  { asm volatile("cp.async.wait_group 0;" ::: "memory"); }
__device__ __forceinline__ void cp_wait1()  { asm volatile("cp.async.wait_group 1;" ::: "memory"); }

__device__ __forceinline__ void ldsm4(uint32_t* r, uint32_t a) {
    asm volatile("ldmatrix.sync.aligned.m8n8.x4.shared.b16 {%0,%1,%2,%3}, [%4];"
                 : "=r"(r[0]), "=r"(r[1]), "=r"(r[2]), "=r"(r[3]) : "r"(a));
}
__device__ __forceinline__ void mma16816(float* c, const uint32_t* a, uint32_t b0, uint32_t b1) {
    asm volatile(
        "mma.sync.aligned.m16n8k16.row.col.f32.bf16.bf16.f32 "
        "{%0,%1,%2,%3}, {%4,%5,%6,%7}, {%8,%9}, {%0,%1,%2,%3};"
        : "+f"(c[0]), "+f"(c[1]), "+f"(c[2]), "+f"(c[3])
        : "r"(a[0]), "r"(a[1]), "r"(a[2]), "r"(a[3]), "r"(b0), "r"(b1));
}

__device__ __forceinline__ void split2(float v0, float v1,
                                       __nv_bfloat162& hp, __nv_bfloat162& lp) {
    __nv_bfloat16 h0 = __float2bfloat16_rn(v0);
    __nv_bfloat16 h1 = __float2bfloat16_rn(v1);
    __nv_bfloat16 l0 = __float2bfloat16_rn(v0 - __bfloat162float(h0));
    __nv_bfloat16 l1 = __float2bfloat16_rn(v1 - __bfloat162float(h1));
    hp.x = h0; hp.y = h1; lp.x = l0; lp.y = l1;
}

// ---------------------------------------------------------------------------
// mma.sync NT GEMM on hi/lo planes: C = alpha*(Ahi·Bhi + Alo·Bhi + Ahi·Blo)
// CTA tile 128xBN, warp tile 64x(BN/4), BK=64, 2-stage cp.async.
// ---------------------------------------------------------------------------
template <int BN>
__global__ void __launch_bounds__(256, 1) mma_gemm(
    const __nv_bfloat16* __restrict__ Ap, long aLo,
    const __nv_bfloat16* __restrict__ Bp, long bLo,
    float* __restrict__ C, int N, int K,
    long sA, long sB, long sC,
    const float* __restrict__ bias, long sBias,
    const float* __restrict__ resid,
    float alpha, int relu2, int packout, long pOfs)
{
    constexpr int NTN = BN / 32;
    constexpr int NTP = BN / 64;
    constexpr uint32_t stALo = 16384u;
    constexpr uint32_t stBhi = 32768u;
    constexpr uint32_t stBlo = 32768u + BN * 128u;
    constexpr uint32_t stSz  = 32768u + 2u * BN * 128u;

    extern __shared__ char smem[];
    const __nv_bfloat16* Ahi = Ap + (long)blockIdx.z * sA;
    const __nv_bfloat16* Alo = Ap + aLo + (long)blockIdx.z * sA;
    const __nv_bfloat16* Bhi = Bp + (long)blockIdx.z * sB;
    const __nv_bfloat16* Blo = Bp + bLo + (long)blockIdx.z * sB;
    C += (long)blockIdx.z * sC;
    if (resid) resid += (long)blockIdx.z * sC;
    if (bias)  bias  += (long)blockIdx.z * sBias;

    const int tid  = threadIdx.x;
    const int lane = tid & 31;
    const int wid  = tid >> 5;
    const int wm   = wid >> 2;
    const int wn   = wid & 3;
    const int row0 = blockIdx.y * 128;
    const int col0 = blockIdx.x * BN;
    const uint32_t su = smem_u32(smem);

    float acc[4][NTN][4];
    #pragma unroll
    for (int mt = 0; mt < 4; mt++)
        #pragma unroll
        for (int nt = 0; nt < NTN; nt++)
            #pragma unroll
            for (int i = 0; i < 4; i++) acc[mt][nt][i] = 0.f;

    const int nch = K >> 6;

    auto load_stage = [&](uint32_t sbase, int k0) {
        #pragma unroll
        for (int i = 0; i < 4; i++) {
            int j = tid + 256 * i; int r = j >> 3, cb = (j & 7) << 4;
            cp16(sbase + sw128((uint32_t)(r * 128 + cb)),
                 Ahi + (long)(row0 + r) * K + k0 + (cb >> 1));
        }
        #pragma unroll
        for (int i = 0; i < 4; i++) {
            int j = tid + 256 * i; int r = j >> 3, cb = (j & 7) << 4;
            cp16(sbase + stALo + sw128((uint32_t)(r * 128 + cb)),
                 Alo + (long)(row0 + r) * K + k0 + (cb >> 1));
        }
        #pragma unroll
        for (int i = 0; i < BN / 32; i++) {
            int j = tid + 256 * i; int r = j >> 3, cb = (j & 7) << 4;
            cp16(sbase + stBhi + sw128((uint32_t)(r * 128 + cb)),
                 Bhi + (long)(col0 + r) * K + k0 + (cb >> 1));
        }
        #pragma unroll
        for (int i = 0; i < BN / 32; i++) {
            int j = tid + 256 * i; int r = j >> 3, cb = (j & 7) << 4;
            cp16(sbase + stBlo + sw128((uint32_t)(r * 128 + cb)),
                 Blo + (long)(col0 + r) * K + k0 + (cb >> 1));
        }
    };

    load_stage(su, 0);
    cp_commit();

    for (int t = 0; t < nch; t++) {
        if (t + 1 < nch) {
            load_stage(su + (((t + 1) & 1) ? stSz : 0u), (t + 1) << 6);
            cp_commit();
            cp_wait1();
        } else {
            cp_wait0();
        }
        __syncthreads();

        const uint32_t sb  = su + ((t & 1) ? stSz : 0u);
        const uint32_t sAh = sb;
        const uint32_t sAl = sb + stALo;
        const uint32_t sBh = sb + stBhi;
        const uint32_t sBl = sb + stBlo;

        #pragma unroll
        for (int ks = 0; ks < 4; ks++) {
            uint32_t ahi[4][4], alo[4][4];
            #pragma unroll
            for (int mt = 0; mt < 4; mt++) {
                uint32_t off = (uint32_t)((wm * 64 + mt * 16 + (lane & 15)) * 128
                                          + ks * 32 + ((lane >> 4) << 4));
                ldsm4(ahi[mt], sAh + sw128(off));
                ldsm4(alo[mt], sAl + sw128(off));
            }
            #pragma unroll
            for (int ntp = 0; ntp < NTP; ntp++) {
                int g = lane >> 3;
                uint32_t off = (uint32_t)((wn * (BN / 4) + ntp * 16 + (lane & 7) + (g >> 1) * 8) * 128
                                          + ks * 32 + (g & 1) * 16);
                uint32_t bh[4], bl[4];
                ldsm4(bh, sBh + sw128(off));
                ldsm4(bl, sBl + sw128(off));
                #pragma unroll
                for (int s = 0; s < 2; s++)
                    #pragma unroll
                    for (int mt = 0; mt < 4; mt++)
                        mma16816(acc[mt][ntp * 2 + s], ahi[mt], bh[2 * s], bh[2 * s + 1]);
                #pragma unroll
                for (int s = 0; s < 2; s++)
                    #pragma unroll
                    for (int mt = 0; mt < 4; mt++)
                        mma16816(acc[mt][ntp * 2 + s], alo[mt], bh[2 * s], bh[2 * s + 1]);
                #pragma unroll
                for (int s = 0; s < 2; s++)
                    #pragma unroll
                    for (int mt = 0; mt < 4; mt++)
                        mma16816(acc[mt][ntp * 2 + s], ahi[mt], bl[2 * s], bl[2 * s + 1]);
            }
        }
        __syncthreads();
    }

    // epilogue
    #pragma unroll
    for (int mt = 0; mt < 4; mt++) {
        int gr0 = row0 + wm * 64 + mt * 16 + (lane >> 2);
        #pragma unroll
        for (int nt = 0; nt < NTN; nt++) {
            int gc = col0 + wn * (BN / 4) + nt * 8 + ((lane & 3) << 1);
            float b0 = 0.f, b1 = 0.f;
            if (bias) { b0 = bias[gc]; b1 = bias[gc + 1]; }
            #pragma unroll
            for (int h = 0; h < 2; h++) {
                int gr = gr0 + h * 8;
                float v0 = acc[mt][nt][h * 2 + 0] * alpha + b0;
                float v1 = acc[mt][nt][h * 2 + 1] * alpha + b1;
                if (relu2) { v0 = fmaxf(v0, 0.f); v0 *= v0;
                             v1 = fmaxf(v1, 0.f); v1 *= v1; }
                if (resid) {
                    float2 rr = *reinterpret_cast<const float2*>(resid + (long)gr * N + gc);
                    v0 += rr.x; v1 += rr.y;
                }
                if (packout) {
                    __nv_bfloat16* P = reinterpret_cast<__nv_bfloat16*>(C);
                    long base = (long)gr * N + gc;
                    __nv_bfloat162 hp, lp;
                    split2(v0, v1, hp, lp);
                    *reinterpret_cast<__nv_bfloat162*>(P + base)        = hp;
                    *reinterpret_cast<__nv_bfloat162*>(P + base + pOfs) = lp;
                } else {
                    *reinterpret_cast<float2*>(C + (long)gr * N + gc) = make_float2(v0, v1);
                }
            }
        }
    }
}

// ---------------------------------------------------------------------------
// packers / small fills
// ---------------------------------------------------------------------------
__global__ void __launch_bounds__(256) split_pack_pl(
    const float* __restrict__ src, __nv_bfloat16* __restrict__ dst,
    long total2, long planeOfs)
{
    long i = (long)blockIdx.x * 256 + threadIdx.x;
    if (i >= total2) return;
    long e = i << 1;
    float2 x = *reinterpret_cast<const float2*>(src + e);
    __nv_bfloat162 hp, lp;
    split2(x.x, x.y, hp, lp);
    *reinterpret_cast<__nv_bfloat162*>(dst + e)            = hp;
    *reinterpret_cast<__nv_bfloat162*>(dst + planeOfs + e) = lp;
}

__global__ void __launch_bounds__(256) fill_b3(
    const float* __restrict__ vb, float* __restrict__ b3)
{
    int i = blockIdx.x * 256 + threadIdx.x;
    if (i < 3 * Dm) b3[i] = (i < 2 * Dm) ? 0.f : vb[i - 2 * Dm];
}

__global__ void __launch_bounds__(128) fill_qkb(
    const float* __restrict__ qb, const float* __restrict__ kb, float* __restrict__ o)
{
    int i = threadIdx.x;
    o[i] = (i < 64) ? qb[i] : kb[i - 64];
}

// split fused qk buffer -> pQ (A planes) and pK (B planes)
__global__ void __launch_bounds__(256) pack_qk(
    const float* __restrict__ qk, __nv_bfloat16* __restrict__ pQ,
    __nv_bfloat16* __restrict__ pK, long planeOfs)
{
    long i2 = (long)blockIdx.x * 256 + threadIdx.x;
    long idx = i2 << 1;
    if (idx >= (long)NT * Am) return;
    long row = idx >> 6;
    int  c = (int)(idx & 63);
    float2 qv = *reinterpret_cast<const float2*>(qk + row * 128 + c);
    float2 kv = *reinterpret_cast<const float2*>(qk + row * 128 + 64 + c);
    __nv_bfloat162 hp, lp;
    long e = row * Am + c;
    split2(qv.x, qv.y, hp, lp);
    *reinterpret_cast<__nv_bfloat162*>(pQ + e)            = hp;
    *reinterpret_cast<__nv_bfloat162*>(pQ + planeOfs + e) = lp;
    split2(kv.x, kv.y, hp, lp);
    *reinterpret_cast<__nv_bfloat162*>(pK + e)            = hp;
    *reinterpret_cast<__nv_bfloat162*>(pK + planeOfs + e) = lp;
}

// ---------------------------------------------------------------------------
// rmsnorm: fp32 out + optional hi/lo plane out
// ---------------------------------------------------------------------------
__global__ void __launch_bounds__(256) rmsnorm_k(
    const float* __restrict__ x, const float* __restrict__ w,
    float* __restrict__ out, __nv_bfloat16* __restrict__ pk, long planeOfs)
{
    int row = blockIdx.x;
    const float* xr = x + (long)row * Dm;
    int tid = threadIdx.x;
    float ss = 0.f;
    #pragma unroll
    for (int d = tid; d < Dm; d += 256) { float v = xr[d]; ss += v * v; }
    __shared__ float red[256];
    red[tid] = ss; __syncthreads();
    for (int o = 128; o; o >>= 1) {
        if (tid < o) red[tid] += red[tid + o];
        __syncthreads();
    }
    float scale = 1.f / (sqrtf(red[0] * (1.f / Dm)) + 1e-8f);
    #pragma unroll
    for (int d = tid; d < Dm; d += 256) {
        float v = w[d] * xr[d] * scale;
        long e = (long)row * Dm + d;
        out[e] = v;
        if (pk) {
            __nv_bfloat16 h = __float2bfloat16_rn(v);
            __nv_bfloat16 l = __float2bfloat16_rn(v - __bfloat162float(h));
            pk[e] = h; pk[e + planeOfs] = l;
        }
    }
}

// ---------------------------------------------------------------------------
// token-shift mixes -> two hi/lo-plane packed A operands
// ---------------------------------------------------------------------------
__global__ void __launch_bounds__(256) mix2pack_k(
    const float* __restrict__ xn, const float* __restrict__ m1,
    const float* __restrict__ m2,
    __nv_bfloat16* __restrict__ p1, __nv_bfloat16* __restrict__ p2, long planeOfs)
{
    long pi2 = (long)blockIdx.x * 256 + threadIdx.x;
    long i = pi2 << 1;
    int d = (int)(i & (Dm - 1));
    int s = (int)((i >> 10) & (Sm - 1));
    long prev = s ? (i - Dm) : i;
    float2 cur = *reinterpret_cast<const float2*>(xn + i);
    float2 prv = *reinterpret_cast<const float2*>(xn + prev);
    float a0 = m1[d], a1 = m1[d + 1];
    float b0 = m2[d], b1 = m2[d + 1];
    float o10 = cur.x * a0 + prv.x * (1.f - a0);
    float o11 = cur.y * a1 + prv.y * (1.f - a1);
    float o20 = cur.x * b0 + prv.x * (1.f - b0);
    float o21 = cur.y * b1 + prv.y * (1.f - b1);
    __nv_bfloat162 hp, lp;
    split2(o10, o11, hp, lp);
    *reinterpret_cast<__nv_bfloat162*>(p1 + i)            = hp;
    *reinterpret_cast<__nv_bfloat162*>(p1 + planeOfs + i) = lp;
    split2(o20, o21, hp, lp);
    *reinterpret_cast<__nv_bfloat162*>(p2 + i)            = hp;
    *reinterpret_cast<__nv_bfloat162*>(p2 + planeOfs + i) = lp;
}

// ---------------------------------------------------------------------------
// top-32 (owner-rescan) + softmax + V-gather -> hi/lo planes
// ---------------------------------------------------------------------------
__global__ void __launch_bounds__(128) topk_attn_k(
    const float* __restrict__ Sc, const float* __restrict__ Vsa,
    __nv_bfloat16* __restrict__ OutP, long planeOfs)
{
    int q = blockIdx.x;
    int b = q >> 12;
    const float* srow = Sc + (long)q * Sm;

    __shared__ float topv[KTOP];
    __shared__ int   topi[KTOP];
    __shared__ float wmv[4];
    __shared__ int   wiv[4];
    __shared__ int   sel;
    __shared__ float p[KTOP];

    const int tid  = threadIdx.x;
    const int lane = tid & 31;
    const int wrp  = tid >> 5;

    float sv[32];
    #pragma unroll
    for (int i = 0; i < 32; i++) sv[i] = srow[tid + (i << 7)];

    float best = -INFINITY; int bloc = 0;
    #pragma unroll
    for (int i = 0; i < 32; i++)
        if (sv[i] > best) { best = sv[i]; bloc = i; }

    for (int it = 0; it < KTOP; it++) {
        float cb = best;
        int   ci = tid + (bloc << 7);
        #pragma unroll
        for (int o = 16; o; o >>= 1) {
            float ov = __shfl_down_sync(0xffffffffu, cb, o);
            int   oi = __shfl_down_sync(0xffffffffu, ci, o);
            if (ov > cb || (ov == cb && oi < ci)) { cb = ov; ci = oi; }
        }
        if (lane == 0) { wmv[wrp] = cb; wiv[wrp] = ci; }
        __syncthreads();
        if (tid == 0) {
            float bb = wmv[0]; int bj = wiv[0];
            #pragma unroll
            for (int w2 = 1; w2 < 4; w2++)
                if (wmv[w2] > bb || (wmv[w2] == bb && wiv[w2] < bj)) { bb = wmv[w2]; bj = wiv[w2]; }
            topv[it] = bb; topi[it] = bj; sel = bj;
        }
        __syncthreads();
        int bj = sel;
        if ((bj & 127) == tid) {
            sv[bj >> 7] = -INFINITY;
            best = -INFINITY; bloc = 0;
            #pragma unroll
            for (int i = 0; i < 32; i++)
                if (sv[i] > best) { best = sv[i]; bloc = i; }
        }
        __syncthreads();
    }

    if (tid == 0) {
        float mx = topv[0], Z = 0.f;
        #pragma unroll
        for (int i2 = 0; i2 < KTOP; i2++) { float e = expf(topv[i2] - mx); p[i2] = e; Z += e; }
        float iz = 1.f / Z;
        #pragma unroll
        for (int i2 = 0; i2 < KTOP; i2++) p[i2] *= iz;
    }
    __syncthreads();

    const float* Vb = Vsa + (long)b * Sm * Dm;
    for (int d = tid; d < Dm; d += 128) {
        float acc = 0.f;
        #pragma unroll
        for (int i2 = 0; i2 < KTOP; i2++)
            acc += p[i2] * Vb[(long)topi[i2] * Dm + d];
        __nv_bfloat16 h = __float2bfloat16_rn(acc);
        __nv_bfloat16 l = __float2bfloat16_rn(acc - __bfloat162float(h));
        long e = (long)q * Dm + d;
        OutP[e] = h; OutP[e + planeOfs] = l;
    }
}

// ---------------------------------------------------------------------------
// gates
// ---------------------------------------------------------------------------
__global__ void __launch_bounds__(256) rkvpack_k(
    const float* __restrict__ r, const float* __restrict__ ao,
    const float* __restrict__ v, __nv_bfloat16* __restrict__ p1, long planeOfs)
{
    long pi2 = (long)blockIdx.x * 256 + threadIdx.x;
    long i = pi2 << 1;
    float2 rr = *reinterpret_cast<const float2*>(r + i);
    float2 aa = *reinterpret_cast<const float2*>(ao + i);
    float2 vv = *reinterpret_cast<const float2*>(v + i);
    float o0 = (1.f / (1.f + expf(-rr.x))) * (aa.x + vv.x);
    float o1 = (1.f / (1.f + expf(-rr.y))) * (aa.y + vv.y);
    __nv_bfloat162 hp, lp;
    split2(o0, o1, hp, lp);
    *reinterpret_cast<__nv_bfloat162*>(p1 + i)            = hp;
    *reinterpret_cast<__nv_bfloat162*>(p1 + planeOfs + i) = lp;
}

__global__ void __launch_bounds__(256) final_k(
    const float* __restrict__ x1, const float* __restrict__ r2,
    const float* __restrict__ kv, float* __restrict__ o)
{
    long i = (long)blockIdx.x * 256 + threadIdx.x;
    float sig = 1.f / (1.f + expf(-r2[i]));
    o[i] = x1[i] + sig * kv[i];
}

// ---------------------------------------------------------------------------
// stream/event context (created once, outside any graph capture)
// ---------------------------------------------------------------------------
struct StreamCtx {
    cudaStream_t s1;
    cudaEvent_t eFork, eXN, eA, eSC, eB, eMix2, eCMR;
    StreamCtx() {
        cudaStreamCreateWithFlags(&s1, cudaStreamNonBlocking);
        unsigned f = cudaEventDisableTiming;
        cudaEventCreateWithFlags(&eFork, f);
        cudaEventCreateWithFlags(&eXN,   f);
        cudaEventCreateWithFlags(&eA,    f);
        cudaEventCreateWithFlags(&eSC,   f);
        cudaEventCreateWithFlags(&eB,    f);
        cudaEventCreateWithFlags(&eMix2, f);
        cudaEventCreateWithFlags(&eCMR,  f);
    }
};
static StreamCtx& sctx() { static StreamCtx c; return c; }

// ---------------------------------------------------------------------------
// launcher
// ---------------------------------------------------------------------------
extern "C" void kernel_launch(void* const* d_in, const int* in_sizes, int n_in,
                              void* d_out, int out_size)
{
    const float* x           = (const float*)d_in[0];
    const float* norm1_w     = (const float*)d_in[1];
    const float* tm_mix_v    = (const float*)d_in[3];
    const float* tm_mix_r    = (const float*)d_in[4];
    // d_in[2]=tm_mix_k, d_in[5]=tm_key_w: dead in reference
    const float* tm_value_w  = (const float*)d_in[6];
    const float* tm_recept_w = (const float*)d_in[7];
    const float* tm_out_w    = (const float*)d_in[8];
    const float* sa_q_w      = (const float*)d_in[9];
    const float* sa_q_b      = (const float*)d_in[10];
    const float* sa_k_w      = (const float*)d_in[11];
    const float* sa_k_b      = (const float*)d_in[12];
    const float* sa_v_w      = (const float*)d_in[13];
    const float* sa_v_b      = (const float*)d_in[14];
    const float* sa_o_w      = (const float*)d_in[15];
    const float* sa_o_b      = (const float*)d_in[16];
    const float* norm2_w     = (const float*)d_in[17];
    const float* cm_mix_k    = (const float*)d_in[18];
    const float* cm_mix_r    = (const float*)d_in[19];
    const float* cm_key_w    = (const float*)d_in[20];
    const float* cm_recept_w = (const float*)d_in[21];
    const float* cm_value_w  = (const float*)d_in[22];
    float* out = (float*)d_out;

    float *xn, *vrv, *ao, *x1, *qk, *big, *b3, *qkb;
    __nv_bfloat16 *pAct, *pBIG, *pQ, *pK, *wAll, *wqk;
    cudaGetSymbolAddress((void**)&xn,   g_xn);
    cudaGetSymbolAddress((void**)&vrv,  g_vrv);
    cudaGetSymbolAddress((void**)&ao,   g_ao);
    cudaGetSymbolAddress((void**)&x1,   g_x1);
    cudaGetSymbolAddress((void**)&qk,   g_qk);
    cudaGetSymbolAddress((void**)&big,  g_big);
    cudaGetSymbolAddress((void**)&b3,   g_b3);
    cudaGetSymbolAddress((void**)&qkb,  g_qkb);
    cudaGetSymbolAddress((void**)&pAct, g_pAct);
    cudaGetSymbolAddress((void**)&pBIG, g_pBIG);
    cudaGetSymbolAddress((void**)&pQ,   g_pQ);
    cudaGetSymbolAddress((void**)&pK,   g_pK);
    cudaGetSymbolAddress((void**)&wAll, g_wAll);
    cudaGetSymbolAddress((void**)&wqk,  g_wqk);

    cudaFuncSetAttribute(mma_gemm<256>, cudaFuncAttributeMaxDynamicSharedMemorySize, 196608);
    cudaFuncSetAttribute(mma_gemm<128>, cudaFuncAttributeMaxDynamicSharedMemorySize, 131072);

    StreamCtx& C = sctx();
    cudaStream_t s1 = C.s1;

    const long ofsD  = (long)NT * Dm;
    const long ofsDI = (long)NT * DIm;
    const long ofsA  = (long)NT * Am;
    const long slot  = 2 * ofsD;
    const long W_DD  = 2L * Dm * Dm;
    const long W_DI  = 2L * DIm * Dm;
    __nv_bfloat16* pS0 = pAct;
    __nv_bfloat16* pS1 = pAct + slot;
    __nv_bfloat16* pS2 = pAct + 2 * slot;
    __nv_bfloat16* w_sao = wAll + 3 * W_DD;
    __nv_bfloat16* w_tmo = wAll + 4 * W_DD;
    __nv_bfloat16* w_cmr = wAll + 5 * W_DD;
    __nv_bfloat16* w_cmk = wAll + 6 * W_DD;
    __nv_bfloat16* w_cmv = wAll + 6 * W_DD + W_DI;

    const dim3 gD (Dm / 256,  NT / 128);
    const dim3 gD3(Dm / 256,  NT / 128, 3);
    const dim3 gDI(DIm / 256, NT / 128);
    const dim3 gS (Sm / 256,  Sm / 128, Bb);
    const dim3 gQK(1, NT / 128);
    const int  pairBlocks = NT * Dm / 512;
    const int  wDDblocks  = (int)((Dm * (long)Dm / 2 + 255) / 256);
    const int  wDIblocks  = (int)((DIm * (long)Dm / 2 + 255) / 256);
    const int  wQKblocks  = (int)((64L * Dm / 2 + 255) / 256);
    const long tDD = Dm * (long)Dm / 2, pDD = (long)Dm * Dm;
    const long tDI = DIm * (long)Dm / 2, pDI = (long)DIm * Dm;

    // ---- fork side stream ----
    cudaEventRecord(C.eFork, 0);
    cudaStreamWaitEvent(s1, C.eFork, 0);

    // ---- main: rmsnorm1 (produces xn + packed pS2) ----
    rmsnorm_k<<<NT, 256>>>(x, norm1_w, xn, pS2, ofsD);
    cudaEventRecord(C.eXN, 0);

    // ---- s1: vrv weight packs + b3 ----
    split_pack_pl<<<wDDblocks, 256, 0, s1>>>(tm_value_w,  wAll,            tDD, pDD);
    split_pack_pl<<<wDDblocks, 256, 0, s1>>>(tm_recept_w, wAll + W_DD,     tDD, pDD);
    split_pack_pl<<<wDDblocks, 256, 0, s1>>>(sa_v_w,      wAll + 2 * W_DD, tDD, pDD);
    fill_b3<<<(3 * Dm + 255) / 256, 256, 0, s1>>>(sa_v_b, b3);
    cudaEventRecord(C.eA, s1);

    // ---- s1: qk chain (weights, bias, gemm, pack, scores) ----
    split_pack_pl<<<wQKblocks, 256, 0, s1>>>(sa_q_w, wqk,           64L * Dm / 2, 128L * Dm);
    split_pack_pl<<<wQKblocks, 256, 0, s1>>>(sa_k_w, wqk + 64 * Dm, 64L * Dm / 2, 128L * Dm);
    fill_qkb<<<1, 128, 0, s1>>>(sa_q_b, sa_k_b, qkb);
    cudaStreamWaitEvent(s1, C.eXN, 0);
    mma_gemm<128><<<gQK, 256, 131072, s1>>>(pS2, ofsD, wqk, 128L * Dm, qk, 128, Dm,
                                            0, 0, 0, qkb, 0, nullptr, 1.f, 0, 0, 0);
    pack_qk<<<(int)((ofsA / 2 + 255) / 256), 256, 0, s1>>>(qk, pQ, pK, ofsA);
    mma_gemm<256><<<gS, 256, 196608, s1>>>(pQ, ofsA, pK, ofsA, big, Sm, Am,
                                           (long)Sm * Am, (long)Sm * Am, (long)Sm * Sm,
                                           nullptr, 0, nullptr, 0.125f, 0, 0, 0);
    cudaEventRecord(C.eSC, s1);

    // ---- s1: remaining weight packs ----
    split_pack_pl<<<wDDblocks, 256, 0, s1>>>(sa_o_w,      w_sao, tDD, pDD);
    split_pack_pl<<<wDDblocks, 256, 0, s1>>>(tm_out_w,    w_tmo, tDD, pDD);
    split_pack_pl<<<wDDblocks, 256, 0, s1>>>(cm_recept_w, w_cmr, tDD, pDD);
    split_pack_pl<<<wDIblocks, 256, 0, s1>>>(cm_key_w,    w_cmk, tDI, pDI);
    split_pack_pl<<<wDIblocks, 256, 0, s1>>>(cm_value_w,  w_cmv, tDI, pDI);
    cudaEventRecord(C.eB, s1);

    // ---- main: mixes + batched v/r/vsa ----
    mix2pack_k<<<pairBlocks, 256>>>(xn, tm_mix_v, tm_mix_r, pS0, pS1, ofsD);
    cudaStreamWaitEvent(0, C.eA, 0);
    mma_gemm<256><<<gD3, 256, 196608>>>(pAct, ofsD, wAll, (long)Dm * Dm, vrv, Dm, Dm,
                                        slot, W_DD, ofsD, b3, Dm, nullptr, 1.f, 0, 0, 0);
    float* v   = vrv;
    float* r   = vrv + ofsD;
    float* vsa = vrv + 2 * ofsD;

    // ---- main: topk (waits on scores from s1) ----
    cudaStreamWaitEvent(0, C.eSC, 0);
    topk_attn_k<<<NT, 128>>>(big, vsa, pS0, ofsD);

    cudaStreamWaitEvent(0, C.eB, 0);
    mma_gemm<256><<<gD, 256, 196608>>>(pS0, ofsD, w_sao, (long)Dm * Dm, ao, Dm, Dm,
                                       0, 0, 0, sa_o_b, 0, nullptr, 1.f, 0, 0, 0);

    rkvpack_k<<<pairBlocks, 256>>>(r, ao, v, pS1, ofsD);

    mma_gemm<256><<<gD, 256, 196608>>>(pS1, ofsD, w_tmo, (long)Dm * Dm, x1, Dm, Dm,
                                       0, 0, 0, nullptr, 0, x, 1.f, 0, 0, 0);

    // ---- channel mix ----
    rmsnorm_k<<<NT, 256>>>(x1, norm2_w, xn, nullptr, 0);
    mix2pack_k<<<pairBlocks, 256>>>(xn, cm_mix_k, cm_mix_r, pS0, pS1, ofsD);
    cudaEventRecord(C.eMix2, 0);

    // s1: r2 = mix2 @ cm_recept (overlaps with cm_key on main)
    cudaStreamWaitEvent(s1, C.eMix2, 0);
    mma_gemm<256><<<gD, 256, 196608, s1>>>(pS1, ofsD, w_cmr, (long)Dm * Dm, r, Dm, Dm,
                                           0, 0, 0, nullptr, 0, nullptr, 1.f, 0, 0, 0);
    cudaEventRecord(C.eCMR, s1);

    // main: k2 = relu^2(mix1 @ cm_key) -> packed
    mma_gemm<256><<<gDI, 256, 196608>>>(pS0, ofsD, w_cmk, (long)DIm * Dm, (float*)pBIG, DIm, Dm,
                                        0, 0, 0, nullptr, 0, nullptr, 1.f, 1, 1, ofsDI);

    // main: v = k2 @ cm_value (needs r2 done)
    cudaStreamWaitEvent(0, C.eCMR, 0);
    mma_gemm<256><<<gD, 256, 196608>>>(pBIG, ofsDI, wAll + 6 * W_DD + W_DI, (long)DIm * Dm, v, Dm, DIm,
                                       0, 0, 0, nullptr, 0, nullptr, 1.f, 0, 0, 0);

    final_k<<<2 * pairBlocks, 256>>>(x1, r, v, out);
}